// round 14
// baseline (speedup 1.0000x reference)
#include <cuda_runtime.h>
#include <cstdint>

#define NTHR 256
#define NW 8
#define GROUP 12
#define ALPHA 0.2f
#define BN_EPS 1e-5f

// ---- smem layout (bytes) ----
// A1 [128][132 f32] = 67584 @0 (120 rows used; dead after GEMM1 dump)
// dump1 [128][72] f32 = 36864 @0        (aliases A1)
// A2   [128][68] f32  = 34816 @36864    (aliases dead A1 tail)
// dump2 [128][40] f32 = 20480 @0        (aliases dump1, dead after epi1)
#define OFF_A2 36864
#define SMEM_BYTES 71680
#define PITCH1 132
#define PITCH2 68
#define PD1 72
#define PD2 40

typedef unsigned long long u64;

// ---- device-global prepared weights ----
__device__ uint4  g_W1F[2304];   // [9 ntile][8 q(k16)][32 lane] {b0e,b1e,b0o,b1o} tf32
__device__ uint4  g_W2F[640];    // [5][4][32]
__device__ float4 g_WLP4[1040];  // [13 c][5 n][16 m]
__device__ float  g_CST[64];     // sc1@0 bi1@8 sc2@16 bi2@24 bl@32

// ------------- helpers -------------
__device__ __forceinline__ uint32_t f2tf32(float v) {
    uint32_t r; asm("cvt.rna.tf32.f32 %0, %1;" : "=r"(r) : "f"(v)); return r;
}
__device__ __forceinline__ void mma_tf32(float* d, const uint32_t* a, uint32_t b0, uint32_t b1) {
    asm volatile("mma.sync.aligned.m16n8k8.row.col.f32.tf32.tf32.f32 "
                 "{%0,%1,%2,%3},{%4,%5,%6,%7},{%8,%9},{%0,%1,%2,%3};"
                 : "+f"(d[0]), "+f"(d[1]), "+f"(d[2]), "+f"(d[3])
                 : "r"(a[0]), "r"(a[1]), "r"(a[2]), "r"(a[3]), "r"(b0), "r"(b1));
}
__device__ __forceinline__ u64 pk2(float a, float b) {
    u64 r; asm("mov.b64 %0, {%1, %2};" : "=l"(r) : "f"(a), "f"(b)); return r;
}
__device__ __forceinline__ float2 upk2(u64 v) {
    float2 r; asm("mov.b64 {%0, %1}, %2;" : "=f"(r.x), "=f"(r.y) : "l"(v)); return r;
}
__device__ __forceinline__ void fma2(u64& d, u64 a, u64 b) {
    asm("fma.rn.f32x2 %0, %1, %2, %3;" : "=l"(d) : "l"(a), "l"(b), "l"(d));
}
__device__ __forceinline__ float lrelu(float v) { return v > 0.f ? v : ALPHA * v; }

// dual-m-tile tf32 GEMM: A from smem rows (conflict-free LDS.32), B frags from global (L1-hot)
template<int NT, int NB, int NQ>
__device__ __forceinline__ void run_gemm2(float (&acc)[2][NT][4], const uint4* __restrict__ WF,
                                          const float* __restrict__ p00, const float* __restrict__ p01,
                                          const float* __restrict__ p10, const float* __restrict__ p11,
                                          int l) {
    #pragma unroll
    for (int mm = 0; mm < 2; ++mm)
        #pragma unroll
        for (int t = 0; t < NT; ++t) { acc[mm][t][0]=0.f; acc[mm][t][1]=0.f; acc[mm][t][2]=0.f; acc[mm][t][3]=0.f; }
    #pragma unroll
    for (int q = 0; q < NQ; ++q) {
        const int k0 = 16 * q;
        uint32_t aE0[4], aO0[4], aE1[4], aO1[4];
        aE0[0] = __float_as_uint(p00[k0]);      aE0[1] = __float_as_uint(p01[k0]);
        aE0[2] = __float_as_uint(p00[k0 + 4]);  aE0[3] = __float_as_uint(p01[k0 + 4]);
        aO0[0] = __float_as_uint(p00[k0 + 8]);  aO0[1] = __float_as_uint(p01[k0 + 8]);
        aO0[2] = __float_as_uint(p00[k0 + 12]); aO0[3] = __float_as_uint(p01[k0 + 12]);
        aE1[0] = __float_as_uint(p10[k0]);      aE1[1] = __float_as_uint(p11[k0]);
        aE1[2] = __float_as_uint(p10[k0 + 4]);  aE1[3] = __float_as_uint(p11[k0 + 4]);
        aO1[0] = __float_as_uint(p10[k0 + 8]);  aO1[1] = __float_as_uint(p11[k0 + 8]);
        aO1[2] = __float_as_uint(p10[k0 + 12]); aO1[3] = __float_as_uint(p11[k0 + 12]);
        #pragma unroll
        for (int t = 0; t < NT; ++t) {
            uint4 bf = WF[((NB + t) * NQ + q) * 32 + l];
            mma_tf32(acc[0][t], aE0, bf.x, bf.y);
            mma_tf32(acc[0][t], aO0, bf.z, bf.w);
            mma_tf32(acc[1][t], aE1, bf.x, bf.y);
            mma_tf32(acc[1][t], aO1, bf.z, bf.w);
        }
    }
}
template<int NT, int NB>
__device__ __forceinline__ void dump_acc2(const float (&acc)[2][NT][4], float* d, int pitch, int i_m, int l) {
    #pragma unroll
    for (int mm = 0; mm < 2; ++mm) {
        int rb = (i_m + 4 * mm) * 16 + (l >> 2);
        #pragma unroll
        for (int t = 0; t < NT; ++t) {
            int c = (NB + t) * 8 + (l & 3) * 2;
            *(float2*)(d + rb * pitch + c)       = make_float2(acc[mm][t][0], acc[mm][t][1]);
            *(float2*)(d + (rb + 8) * pitch + c) = make_float2(acc[mm][t][2], acc[mm][t][3]);
        }
    }
}

// ================= prep kernel: 8 blocks x 512, scores computed redundantly =================
__global__ void __launch_bounds__(512, 1)
prep(const float* __restrict__ Wt1, const float* __restrict__ a11, const float* __restrict__ a21,
     const float* __restrict__ Wt2, const float* __restrict__ a12, const float* __restrict__ a22,
     const float* __restrict__ Wl, const float* __restrict__ bl,
     const float* __restrict__ g1, const float* __restrict__ b1,
     const float* __restrict__ m1, const float* __restrict__ v1,
     const float* __restrict__ g2, const float* __restrict__ b2,
     const float* __restrict__ m2, const float* __restrict__ v2)
{
    __shared__ float s_score[512];
    const int t = threadIdx.x;
    const int blk = blockIdx.x;

    // W1 scores: all 512 threads (4 per k)
    {
        int k = t >> 2, s = t & 3;
        float sa = 0.f, sb = 0.f;
        if (k < 125) {
            #pragma unroll 4
            for (int oo = 0; oo < 16; ++oo) {
                int o = s * 16 + oo;
                float wv = Wt1[o * 125 + k];
                sa = fmaf(a11[o], wv, sa); sb = fmaf(a21[o], wv, sb);
            }
        }
        sa += __shfl_xor_sync(0xffffffffu, sa, 1); sa += __shfl_xor_sync(0xffffffffu, sa, 2);
        sb += __shfl_xor_sync(0xffffffffu, sb, 1); sb += __shfl_xor_sync(0xffffffffu, sb, 2);
        if (s == 0) { s_score[k] = sa; s_score[128 + k] = sb; }
    }
    // W2 scores: first 256 threads (4 per k)
    if (t < 256) {
        int k = t >> 2, s = t & 3;
        float sa = 0.f, sb = 0.f;
        #pragma unroll
        for (int oo = 0; oo < 8; ++oo) {
            int o = s * 8 + oo;
            float wv = Wt2[o * 64 + k];
            sa = fmaf(a12[o], wv, sa); sb = fmaf(a22[o], wv, sb);
        }
        sa += __shfl_xor_sync(0xffffffffu, sa, 1); sa += __shfl_xor_sync(0xffffffffu, sa, 2);
        sb += __shfl_xor_sync(0xffffffffu, sb, 1); sb += __shfl_xor_sync(0xffffffffu, sb, 2);
        if (s == 0) { s_score[256 + k] = sa; s_score[384 + k] = sb; }
    }
    __syncthreads();

    const int gt = blk * 512 + t;   // 0..4095

    if (blk == 0) {
        if (t < 5) {
            float s = g1[t] * rsqrtf(v1[t] + BN_EPS);
            g_CST[t] = s; g_CST[8 + t] = b1[t] - m1[t] * s;
        } else if (t >= 8 && t < 13) {
            int i = t - 8;
            float s = g2[i] * rsqrtf(v2[i] + BN_EPS);
            g_CST[16 + i] = s; g_CST[24 + i] = b2[i] - m2[i] * s;
        } else if (t >= 16 && t < 29) {
            g_CST[32 + (t - 16)] = bl[t - 16];
        }
    }
    if (gt < 1040) {
        int c = gt / 80, rem = gt - c * 80;
        int n = rem >> 4, m = rem & 15;
        const float* wr = Wl + c * 320 + n * 64 + 2 * m;
        g_WLP4[gt] = make_float4(wr[0], wr[1], wr[32], wr[33]);
    }
    if (gt < 2304) {
        int T = gt >> 8, q = (gt >> 5) & 7, L = gt & 31;
        int g = L >> 2, tt = L & 3;
        int nn = T * 8 + g;
        uint32_t v[4];
        #pragma unroll
        for (int i = 0; i < 4; ++i) {
            int k = 16 * q + (i >> 1) * 8 + (i & 1) * 4 + tt;
            float vv = 0.f;
            if (k < 125) {
                if (nn < 64)      vv = Wt1[nn * 125 + k];
                else if (nn == 64) vv = s_score[k];
                else if (nn == 65) vv = s_score[128 + k];
            }
            v[i] = f2tf32(vv);
        }
        g_W1F[gt] = make_uint4(v[0], v[1], v[2], v[3]);
    }
    if (gt < 640) {
        int T = gt >> 7, q = (gt >> 5) & 3, L = gt & 31;
        int g = L >> 2, tt = L & 3;
        int nn = T * 8 + g;
        uint32_t v[4];
        #pragma unroll
        for (int i = 0; i < 4; ++i) {
            int k = 16 * q + (i >> 1) * 8 + (i & 1) * 4 + tt;
            float vv = 0.f;
            if (nn < 32)      vv = Wt2[nn * 64 + k];
            else if (nn == 32) vv = s_score[256 + k];
            else if (nn == 33) vv = s_score[384 + k];
            v[i] = f2tf32(vv);
        }
        g_W2F[gt] = make_uint4(v[0], v[1], v[2], v[3]);
    }
}

// ================= main fused kernel =================
__global__ void __launch_bounds__(NTHR, 3)
gat14_kernel(const float* __restrict__ x, float* __restrict__ out, int B)
{
    extern __shared__ __align__(16) char smc[];
    const int tid = threadIdx.x;
    const int w = tid >> 5, l = tid & 31;
    const int b0 = blockIdx.x * GROUP;
    float* A1 = (float*)smc;
    float* A2 = (float*)(smc + OFF_A2);

    // ---- stage x -> A1 rows 0..127 (tf32, pitch 132, conflict-free; rows>=120 zero) ----
    {
        #pragma unroll
        for (int j = 0; j < 16; ++j) {
            int r = j * NW + w;
            int lb = r / 10, rem = r - lb * 10;
            int p = rem / 5, n = rem - p * 5;
            bool rv = (r < 120) && (b0 + lb < B);
            const float* src = x + (size_t)(b0 + lb) * 1250 + n * 250 + p * 125;
            float* arow = A1 + r * PITCH1;
            #pragma unroll
            for (int i = 0; i < 4; ++i) {
                int k = l + 32 * i;
                float v = (rv && k < 125) ? src[k] : 0.f;
                *(uint32_t*)(arow + k) = f2tf32(v);
            }
        }
    }
    __syncthreads();

    const int i_m = w & 3, j_n = w >> 2;
    const int g = l >> 2, tt = l & 3;
    float* d1 = A1;                      // dump region aliases A1

    // ---- GEMM1: A[128x128] x W1frag[72x128] -> dump1 [128][72], m-tile pairs ----
    {
        const float* p00 = A1 + (i_m * 16 + g) * PITCH1 + tt;
        const float* p01 = p00 + 8 * PITCH1;
        const float* p10 = A1 + ((i_m + 4) * 16 + g) * PITCH1 + tt;
        const float* p11 = p10 + 8 * PITCH1;
        if (j_n == 0) {
            float acc[2][5][4];
            run_gemm2<5, 0, 8>(acc, g_W1F, p00, p01, p10, p11, l);
            __syncthreads();
            dump_acc2<5, 0>(acc, d1, PD1, i_m, l);
        } else {
            float acc[2][4][4];
            run_gemm2<4, 5, 8>(acc, g_W1F, p00, p01, p10, p11, l);
            __syncthreads();
            dump_acc2<4, 5>(acc, d1, PD1, i_m, l);
        }
    }
    __syncthreads();

    // ---- epilogue 1 (half-warp dual-path): warp covers batches {w, w+8} ----
    for (int u = w; u < GROUP; u += NW) {
        const int half = l >> 4, m = l & 15;     // lane m covers cols 4m..4m+3
        const int rb = u * 10 + half * 5;
        float s1[5], s2[5];
        #pragma unroll
        for (int n = 0; n < 5; ++n) {
            float2 sv = *(const float2*)(d1 + (rb + n) * PD1 + 64);
            s1[n] = sv.x; s2[n] = sv.y;
        }
        u64 oA[5], oB[5];
        #pragma unroll
        for (int n = 0; n < 5; ++n) { oA[n] = 0ull; oB[n] = 0ull; }
        #pragma unroll
        for (int j = 0; j < 5; ++j) {
            ulonglong2 hj = *(const ulonglong2*)(d1 + (rb + j) * PD1 + 4 * m);
            float e[5]; float Z = 0.f;
            #pragma unroll
            for (int i = 0; i < 5; ++i) { e[i] = __expf(lrelu(s1[i] + s2[j])); Z += e[i]; }
            float rz = __fdividef(1.f, Z);
            #pragma unroll
            for (int i = 0; i < 5; ++i) {
                float wv = e[i] * rz;
                u64 wv2 = pk2(wv, wv);
                fma2(oA[i], wv2, hj.x);
                fma2(oB[i], wv2, hj.y);
            }
        }
        #pragma unroll
        for (int i = 0; i < 5; ++i) {
            float sc = g_CST[i], bi = g_CST[8 + i];
            float2 a = upk2(oA[i]), b = upk2(oB[i]);
            uint4 pkd;
            pkd.x = f2tf32(fmaxf(fmaf(a.x, sc, bi), 0.f));
            pkd.y = f2tf32(fmaxf(fmaf(a.y, sc, bi), 0.f));
            pkd.z = f2tf32(fmaxf(fmaf(b.x, sc, bi), 0.f));
            pkd.w = f2tf32(fmaxf(fmaf(b.y, sc, bi), 0.f));
            *(uint4*)(A2 + (rb + i) * PITCH2 + 4 * m) = pkd;
        }
    }
    // zero-pad A2 rows 120..127 (GEMM2 reads them; avoid stale tf32 garbage)
    {
        int r = 120 + w;
        float* arow = A2 + r * PITCH2;
        *(uint2*)(arow + 2 * l) = make_uint2(0u, 0u);
    }
    __syncthreads();

    // ---- GEMM2: A2[128x64] x W2frag[40x64] -> dump2 [128][40] @ region0 ----
    float* d2 = A1;
    {
        const float* p00 = A2 + (i_m * 16 + g) * PITCH2 + tt;
        const float* p01 = p00 + 8 * PITCH2;
        const float* p10 = A2 + ((i_m + 4) * 16 + g) * PITCH2 + tt;
        const float* p11 = p10 + 8 * PITCH2;
        if (j_n == 0) {
            float acc[2][3][4];
            run_gemm2<3, 0, 4>(acc, g_W2F, p00, p01, p10, p11, l);
            dump_acc2<3, 0>(acc, d2, PD2, i_m, l);
        } else {
            float acc[2][2][4];
            run_gemm2<2, 3, 4>(acc, g_W2F, p00, p01, p10, p11, l);
            dump_acc2<2, 3>(acc, d2, PD2, i_m, l);
        }
    }
    __syncthreads();

    // ---- epilogue 2 (3 warps x 4 batches; half-warp = batch, 2 serial per half) ----
    // Wl table is streamed once per WARP, so fewer epi2 warps = less L1 traffic.
    if (w < 3) {
        const int half = l >> 4, m = l & 15;     // lane m covers cols 2m,2m+1
        const ulonglong2* WLP = (const ulonglong2*)g_WLP4;
        #pragma unroll
        for (int b2 = 0; b2 < 2; ++b2) {
            const int u = 4 * w + 2 * half + b2;
            const int rA = u * 10, rN = rA + 5;
            float s1a[5], s2a[5], s1b[5], s2b[5];
            #pragma unroll
            for (int n = 0; n < 5; ++n) {
                float2 sA = *(const float2*)(d2 + (rA + n) * PD2 + 32);  // (hA@a12, hA@a22)
                float2 sN = *(const float2*)(d2 + (rN + n) * PD2 + 32);  // (hN@a12, hN@a22)
                s1a[n] = sA.x; s2b[n] = sA.y;
                s1b[n] = sN.x; s2a[n] = sN.y;
            }
            u64 oA2[5], oN2[5];
            #pragma unroll
            for (int n = 0; n < 5; ++n) { oA2[n] = 0ull; oN2[n] = 0ull; }
            #pragma unroll
            for (int j = 0; j < 5; ++j) {
                u64 hAj = *(const u64*)(d2 + (rA + j) * PD2 + 2 * m);
                u64 hNj = *(const u64*)(d2 + (rN + j) * PD2 + 2 * m);
                float eA[5], eN[5]; float ZA = 0.f, ZN = 0.f;
                #pragma unroll
                for (int i = 0; i < 5; ++i) {
                    eA[i] = __expf(lrelu(s1a[i] + s2a[j])); ZA += eA[i];
                    eN[i] = __expf(lrelu(s1b[i] + s2b[j])); ZN += eN[i];
                }
                float rzA = __fdividef(1.f, ZA), rzN = __fdividef(1.f, ZN);
                #pragma unroll
                for (int i = 0; i < 5; ++i) {
                    float wa = eA[i] * rzA, wn = eN[i] * rzN;
                    fma2(oA2[i], pk2(wa, wa), hAj);
                    fma2(oN2[i], pk2(wn, wn), hNj);
                }
            }
            u64 fa2[5], fb2[5];
            #pragma unroll
            for (int n = 0; n < 5; ++n) {
                float sc = g_CST[16 + n], bi = g_CST[24 + n];
                float2 a = upk2(oA2[n]), b = upk2(oN2[n]);
                fa2[n] = pk2(fmaxf(fmaf(a.x, sc, bi), 0.f), fmaxf(fmaf(a.y, sc, bi), 0.f));
                fb2[n] = pk2(fmaxf(fmaf(b.x, sc, bi), 0.f), fmaxf(fmaf(b.y, sc, bi), 0.f));
            }
            float ov = 0.f;
            #pragma unroll
            for (int c = 0; c < 13; ++c) {
                u64 a2 = 0ull;
                #pragma unroll
                for (int n = 0; n < 5; ++n) {
                    ulonglong2 wl = WLP[(c * 5 + n) * 16 + m];
                    fma2(a2, fa2[n], wl.x);
                    fma2(a2, fb2[n], wl.y);
                }
                float2 p = upk2(a2);
                float v = p.x + p.y;
                v += __shfl_xor_sync(0xffffffffu, v, 8);
                v += __shfl_xor_sync(0xffffffffu, v, 4);
                v += __shfl_xor_sync(0xffffffffu, v, 2);
                v += __shfl_xor_sync(0xffffffffu, v, 1);
                if (m == c) ov = v;
            }
            int bb = b0 + u;
            if (m < 13 && bb < B)
                out[(size_t)bb * 13 + m] = ov + g_CST[32 + m];
        }
    }
}

extern "C" void kernel_launch(void* const* d_in, const int* in_sizes, int n_in,
                              void* d_out, int out_size)
{
    const float* x   = (const float*)d_in[0];
    const float* Wt1 = (const float*)d_in[1];
    const float* a11 = (const float*)d_in[2];
    const float* a21 = (const float*)d_in[3];
    const float* g1  = (const float*)d_in[4];
    const float* b1  = (const float*)d_in[5];
    const float* m1  = (const float*)d_in[6];
    const float* v1  = (const float*)d_in[7];
    const float* Wt2 = (const float*)d_in[8];
    const float* a12 = (const float*)d_in[9];
    const float* a22 = (const float*)d_in[10];
    const float* g2  = (const float*)d_in[11];
    const float* b2  = (const float*)d_in[12];
    const float* m2  = (const float*)d_in[13];
    const float* v2  = (const float*)d_in[14];
    const float* Wl  = (const float*)d_in[15];
    const float* bl  = (const float*)d_in[16];

    int B = in_sizes[0] / 1250;
    prep<<<8, 512>>>(Wt1, a11, a21, Wt2, a12, a22, Wl, bl,
                     g1, b1, m1, v1, g2, b2, m2, v2);
    int grid = (B + GROUP - 1) / GROUP;
    cudaFuncSetAttribute(gat14_kernel, cudaFuncAttributeMaxDynamicSharedMemorySize, SMEM_BYTES);
    cudaFuncSetAttribute(gat14_kernel, cudaFuncAttributePreferredSharedMemoryCarveout, 100);
    gat14_kernel<<<grid, NTHR, SMEM_BYTES>>>(x, (float*)d_out, B);
}

// round 15
// speedup vs baseline: 1.7254x; 1.7254x over previous
#include <cuda_runtime.h>
#include <cstdint>

#define NTHR 256
#define NW 8
#define GROUP 12
#define ALPHA 0.2f
#define BN_EPS 1e-5f

// ---- smem layout (bytes) ----
// A1 [128][132 f32] = 67584 @0 (120 rows used; dead after GEMM1 dump)
// dump1 [128][72] f32 = 36864 @0        (aliases A1)
// A2   [128][68] f32  = 34816 @36864    (aliases dead A1 tail)
// dump2 [128][40] f32 = 20480 @0        (aliases dump1, dead after epi1)
#define OFF_A2 36864
#define SMEM_BYTES 71680
#define PITCH1 132
#define PITCH2 68
#define PD1 72
#define PD2 40

typedef unsigned long long u64;

// ---- device-global prepared weights ----
__device__ uint4  g_W1F[2304];   // [9 ntile][8 q(k16)][32 lane] {b0e,b1e,b0o,b1o} tf32
__device__ uint4  g_W2F[640];    // [5][4][32]
__device__ float2 g_WLP[2080];   // [13 c][5 n][32 l]
__device__ float4 g_WLP4[1040];  // [13 c][5 n][16 m]
__device__ float  g_CST[64];     // sc1@0 bi1@8 sc2@16 bi2@24 bl@32

// ------------- helpers -------------
__device__ __forceinline__ uint32_t f2tf32(float v) {
    uint32_t r; asm("cvt.rna.tf32.f32 %0, %1;" : "=r"(r) : "f"(v)); return r;
}
__device__ __forceinline__ void mma_tf32(float* d, const uint32_t* a, uint32_t b0, uint32_t b1) {
    asm volatile("mma.sync.aligned.m16n8k8.row.col.f32.tf32.tf32.f32 "
                 "{%0,%1,%2,%3},{%4,%5,%6,%7},{%8,%9},{%0,%1,%2,%3};"
                 : "+f"(d[0]), "+f"(d[1]), "+f"(d[2]), "+f"(d[3])
                 : "r"(a[0]), "r"(a[1]), "r"(a[2]), "r"(a[3]), "r"(b0), "r"(b1));
}
__device__ __forceinline__ u64 pk2(float a, float b) {
    u64 r; asm("mov.b64 %0, {%1, %2};" : "=l"(r) : "f"(a), "f"(b)); return r;
}
__device__ __forceinline__ float2 upk2(u64 v) {
    float2 r; asm("mov.b64 {%0, %1}, %2;" : "=f"(r.x), "=f"(r.y) : "l"(v)); return r;
}
__device__ __forceinline__ void fma2(u64& d, u64 a, u64 b) {
    asm("fma.rn.f32x2 %0, %1, %2, %3;" : "=l"(d) : "l"(a), "l"(b), "l"(d));
}
__device__ __forceinline__ float lrelu(float v) { return v > 0.f ? v : ALPHA * v; }

// dual-m-tile tf32 GEMM: A from smem rows (conflict-free LDS.32), B frags from global (L1-hot)
template<int NT, int NB, int NQ>
__device__ __forceinline__ void run_gemm2(float (&acc)[2][NT][4], const uint4* __restrict__ WF,
                                          const float* __restrict__ p00, const float* __restrict__ p01,
                                          const float* __restrict__ p10, const float* __restrict__ p11,
                                          int l) {
    #pragma unroll
    for (int mm = 0; mm < 2; ++mm)
        #pragma unroll
        for (int t = 0; t < NT; ++t) { acc[mm][t][0]=0.f; acc[mm][t][1]=0.f; acc[mm][t][2]=0.f; acc[mm][t][3]=0.f; }
    #pragma unroll
    for (int q = 0; q < NQ; ++q) {
        const int k0 = 16 * q;
        uint32_t aE0[4], aO0[4], aE1[4], aO1[4];
        aE0[0] = __float_as_uint(p00[k0]);      aE0[1] = __float_as_uint(p01[k0]);
        aE0[2] = __float_as_uint(p00[k0 + 4]);  aE0[3] = __float_as_uint(p01[k0 + 4]);
        aO0[0] = __float_as_uint(p00[k0 + 8]);  aO0[1] = __float_as_uint(p01[k0 + 8]);
        aO0[2] = __float_as_uint(p00[k0 + 12]); aO0[3] = __float_as_uint(p01[k0 + 12]);
        aE1[0] = __float_as_uint(p10[k0]);      aE1[1] = __float_as_uint(p11[k0]);
        aE1[2] = __float_as_uint(p10[k0 + 4]);  aE1[3] = __float_as_uint(p11[k0 + 4]);
        aO1[0] = __float_as_uint(p10[k0 + 8]);  aO1[1] = __float_as_uint(p11[k0 + 8]);
        aO1[2] = __float_as_uint(p10[k0 + 12]); aO1[3] = __float_as_uint(p11[k0 + 12]);
        #pragma unroll
        for (int t = 0; t < NT; ++t) {
            uint4 bf = WF[((NB + t) * NQ + q) * 32 + l];
            mma_tf32(acc[0][t], aE0, bf.x, bf.y);
            mma_tf32(acc[0][t], aO0, bf.z, bf.w);
            mma_tf32(acc[1][t], aE1, bf.x, bf.y);
            mma_tf32(acc[1][t], aO1, bf.z, bf.w);
        }
    }
}
template<int NT, int NB>
__device__ __forceinline__ void dump_acc2(const float (&acc)[2][NT][4], float* d, int pitch, int i_m, int l) {
    #pragma unroll
    for (int mm = 0; mm < 2; ++mm) {
        int rb = (i_m + 4 * mm) * 16 + (l >> 2);
        #pragma unroll
        for (int t = 0; t < NT; ++t) {
            int c = (NB + t) * 8 + (l & 3) * 2;
            *(float2*)(d + rb * pitch + c)       = make_float2(acc[mm][t][0], acc[mm][t][1]);
            *(float2*)(d + (rb + 8) * pitch + c) = make_float2(acc[mm][t][2], acc[mm][t][3]);
        }
    }
}

// ================= single merged prep kernel (1 block, 1024 threads) =================
__global__ void __launch_bounds__(1024, 1)
prep(const float* __restrict__ Wt1, const float* __restrict__ a11, const float* __restrict__ a21,
     const float* __restrict__ Wt2, const float* __restrict__ a12, const float* __restrict__ a22,
     const float* __restrict__ Wl, const float* __restrict__ bl,
     const float* __restrict__ g1, const float* __restrict__ b1,
     const float* __restrict__ m1, const float* __restrict__ v1,
     const float* __restrict__ g2, const float* __restrict__ b2,
     const float* __restrict__ m2, const float* __restrict__ v2)
{
    __shared__ float s_score[512];
    const int t = threadIdx.x;

    if (t < 512) {
        int k = t >> 2, s = t & 3;
        float sa = 0.f, sb = 0.f;
        if (k < 125) {
            #pragma unroll 4
            for (int oo = 0; oo < 16; ++oo) {
                int o = s * 16 + oo;
                float wv = Wt1[o * 125 + k];
                sa = fmaf(a11[o], wv, sa); sb = fmaf(a21[o], wv, sb);
            }
        }
        sa += __shfl_xor_sync(0xffffffffu, sa, 1); sa += __shfl_xor_sync(0xffffffffu, sa, 2);
        sb += __shfl_xor_sync(0xffffffffu, sb, 1); sb += __shfl_xor_sync(0xffffffffu, sb, 2);
        if (s == 0) { s_score[k] = sa; s_score[128 + k] = sb; }
    } else if (t < 768) {
        int k = (t - 512) >> 2, s = t & 3;
        float sa = 0.f, sb = 0.f;
        #pragma unroll
        for (int oo = 0; oo < 8; ++oo) {
            int o = s * 8 + oo;
            float wv = Wt2[o * 64 + k];
            sa = fmaf(a12[o], wv, sa); sb = fmaf(a22[o], wv, sb);
        }
        sa += __shfl_xor_sync(0xffffffffu, sa, 1); sa += __shfl_xor_sync(0xffffffffu, sa, 2);
        sb += __shfl_xor_sync(0xffffffffu, sb, 1); sb += __shfl_xor_sync(0xffffffffu, sb, 2);
        if (s == 0) { s_score[256 + k] = sa; s_score[384 + k] = sb; }
    } else if (t >= 800 && t < 805) {
        int i = t - 800;
        float s = g1[i] * rsqrtf(v1[i] + BN_EPS);
        g_CST[i] = s; g_CST[8 + i] = b1[i] - m1[i] * s;
    } else if (t >= 805 && t < 810) {
        int i = t - 805;
        float s = g2[i] * rsqrtf(v2[i] + BN_EPS);
        g_CST[16 + i] = s; g_CST[24 + i] = b2[i] - m2[i] * s;
    } else if (t >= 810 && t < 823) {
        g_CST[32 + (t - 810)] = bl[t - 810];
    }
    for (int e = t; e < 1040; e += 1024) {
        int c = e / 80, rem = e - c * 80;
        int n = rem >> 4, m = rem & 15;
        const float* wr = Wl + c * 320 + n * 64 + 2 * m;
        g_WLP4[e] = make_float4(wr[0], wr[1], wr[32], wr[33]);
    }
    __syncthreads();

    for (int e = t; e < 2304; e += 1024) {
        int T = e >> 8, q = (e >> 5) & 7, L = e & 31;
        int g = L >> 2, tt = L & 3;
        int nn = T * 8 + g;
        uint32_t v[4];
        #pragma unroll
        for (int i = 0; i < 4; ++i) {
            int k = 16 * q + (i >> 1) * 8 + (i & 1) * 4 + tt;
            float vv = 0.f;
            if (k < 125) {
                if (nn < 64)      vv = Wt1[nn * 125 + k];
                else if (nn == 64) vv = s_score[k];
                else if (nn == 65) vv = s_score[128 + k];
            }
            v[i] = f2tf32(vv);
        }
        g_W1F[e] = make_uint4(v[0], v[1], v[2], v[3]);
    }
    for (int f = t; f < 640; f += 1024) {
        int T = f >> 7, q = (f >> 5) & 3, L = f & 31;
        int g = L >> 2, tt = L & 3;
        int nn = T * 8 + g;
        uint32_t v[4];
        #pragma unroll
        for (int i = 0; i < 4; ++i) {
            int k = 16 * q + (i >> 1) * 8 + (i & 1) * 4 + tt;
            float vv = 0.f;
            if (nn < 32)      vv = Wt2[nn * 64 + k];
            else if (nn == 32) vv = s_score[256 + k];
            else if (nn == 33) vv = s_score[384 + k];
            v[i] = f2tf32(vv);
        }
        g_W2F[f] = make_uint4(v[0], v[1], v[2], v[3]);
    }
}

// ================= main fused kernel =================
__global__ void __launch_bounds__(NTHR, 3)
gat15_kernel(const float* __restrict__ x, float* __restrict__ out, int B)
{
    extern __shared__ __align__(16) char smc[];
    const int tid = threadIdx.x;
    const int w = tid >> 5, l = tid & 31;
    const int b0 = blockIdx.x * GROUP;
    float* A1 = (float*)smc;
    float* A2 = (float*)(smc + OFF_A2);

    // ---- stage x -> A1 rows 0..127 (tf32, pitch 132, conflict-free; rows>=120 zero) ----
    {
        #pragma unroll
        for (int j = 0; j < 16; ++j) {
            int r = j * NW + w;
            int lb = r / 10, rem = r - lb * 10;
            int p = rem / 5, n = rem - p * 5;
            bool rv = (r < 120) && (b0 + lb < B);
            const float* src = x + (size_t)(b0 + lb) * 1250 + n * 250 + p * 125;
            float* arow = A1 + r * PITCH1;
            #pragma unroll
            for (int i = 0; i < 4; ++i) {
                int k = l + 32 * i;
                float v = (rv && k < 125) ? src[k] : 0.f;
                *(uint32_t*)(arow + k) = f2tf32(v);
            }
        }
    }
    __syncthreads();

    const int i_m = w & 3, j_n = w >> 2;
    const int g = l >> 2, tt = l & 3;
    float* d1 = A1;                      // dump region aliases A1

    // ---- GEMM1: A[128x128] x W1frag[72x128] -> dump1 [128][72], m-tile pairs ----
    {
        const float* p00 = A1 + (i_m * 16 + g) * PITCH1 + tt;
        const float* p01 = p00 + 8 * PITCH1;
        const float* p10 = A1 + ((i_m + 4) * 16 + g) * PITCH1 + tt;
        const float* p11 = p10 + 8 * PITCH1;
        if (j_n == 0) {
            float acc[2][5][4];
            run_gemm2<5, 0, 8>(acc, g_W1F, p00, p01, p10, p11, l);
            __syncthreads();
            dump_acc2<5, 0>(acc, d1, PD1, i_m, l);
        } else {
            float acc[2][4][4];
            run_gemm2<4, 5, 8>(acc, g_W1F, p00, p01, p10, p11, l);
            __syncthreads();
            dump_acc2<4, 5>(acc, d1, PD1, i_m, l);
        }
    }
    __syncthreads();

    // ---- epilogue 1 (half-warp dual-path): warp covers batches {w, w+8} ----
    for (int u = w; u < GROUP; u += NW) {
        const int half = l >> 4, m = l & 15;     // lane m covers cols 4m..4m+3
        const int rb = u * 10 + half * 5;
        float s1[5], s2[5];
        #pragma unroll
        for (int n = 0; n < 5; ++n) {
            float2 sv = *(const float2*)(d1 + (rb + n) * PD1 + 64);
            s1[n] = sv.x; s2[n] = sv.y;
        }
        u64 oA[5], oB[5];
        #pragma unroll
        for (int n = 0; n < 5; ++n) { oA[n] = 0ull; oB[n] = 0ull; }
        #pragma unroll
        for (int j = 0; j < 5; ++j) {
            ulonglong2 hj = *(const ulonglong2*)(d1 + (rb + j) * PD1 + 4 * m);
            float e[5]; float Z = 0.f;
            #pragma unroll
            for (int i = 0; i < 5; ++i) { e[i] = __expf(lrelu(s1[i] + s2[j])); Z += e[i]; }
            float rz = __fdividef(1.f, Z);
            #pragma unroll
            for (int i = 0; i < 5; ++i) {
                float wv = e[i] * rz;
                u64 wv2 = pk2(wv, wv);
                fma2(oA[i], wv2, hj.x);
                fma2(oB[i], wv2, hj.y);
            }
        }
        #pragma unroll
        for (int i = 0; i < 5; ++i) {
            float sc = g_CST[i], bi = g_CST[8 + i];
            float2 a = upk2(oA[i]), b = upk2(oB[i]);
            uint4 pkd;
            pkd.x = f2tf32(fmaxf(fmaf(a.x, sc, bi), 0.f));
            pkd.y = f2tf32(fmaxf(fmaf(a.y, sc, bi), 0.f));
            pkd.z = f2tf32(fmaxf(fmaf(b.x, sc, bi), 0.f));
            pkd.w = f2tf32(fmaxf(fmaf(b.y, sc, bi), 0.f));
            *(uint4*)(A2 + (rb + i) * PITCH2 + 4 * m) = pkd;
        }
    }
    // zero-pad A2 rows 120..127 (GEMM2 reads them; avoid stale tf32 garbage)
    {
        int r = 120 + w;
        float* arow = A2 + r * PITCH2;
        *(uint2*)(arow + 2 * l) = make_uint2(0u, 0u);
    }
    __syncthreads();

    // ---- GEMM2: A2[128x64] x W2frag[40x64] -> dump2 [128][40] @ region0 ----
    float* d2 = A1;
    {
        const float* p00 = A2 + (i_m * 16 + g) * PITCH2 + tt;
        const float* p01 = p00 + 8 * PITCH2;
        const float* p10 = A2 + ((i_m + 4) * 16 + g) * PITCH2 + tt;
        const float* p11 = p10 + 8 * PITCH2;
        if (j_n == 0) {
            float acc[2][3][4];
            run_gemm2<3, 0, 4>(acc, g_W2F, p00, p01, p10, p11, l);
            dump_acc2<3, 0>(acc, d2, PD2, i_m, l);
        } else {
            float acc[2][2][4];
            run_gemm2<2, 3, 4>(acc, g_W2F, p00, p01, p10, p11, l);
            dump_acc2<2, 3>(acc, d2, PD2, i_m, l);
        }
    }
    __syncthreads();

    // ---- epilogue 2 (half-warp dual-batch): warps 0..5 cover u = 2w + half ----
    if (w < 6) {
        const int half = l >> 4, m = l & 15;     // lane m covers cols 2m,2m+1
        const int u = 2 * w + half;
        const int rA = u * 10, rN = rA + 5;
        float s1a[5], s2a[5], s1b[5], s2b[5];
        #pragma unroll
        for (int n = 0; n < 5; ++n) {
            float2 sA = *(const float2*)(d2 + (rA + n) * PD2 + 32);  // (hA@a12, hA@a22)
            float2 sN = *(const float2*)(d2 + (rN + n) * PD2 + 32);  // (hN@a12, hN@a22)
            s1a[n] = sA.x; s2b[n] = sA.y;
            s1b[n] = sN.x; s2a[n] = sN.y;
        }
        u64 oA2[5], oN2[5];
        #pragma unroll
        for (int n = 0; n < 5; ++n) { oA2[n] = 0ull; oN2[n] = 0ull; }
        #pragma unroll
        for (int j = 0; j < 5; ++j) {
            u64 hAj = *(const u64*)(d2 + (rA + j) * PD2 + 2 * m);
            u64 hNj = *(const u64*)(d2 + (rN + j) * PD2 + 2 * m);
            float eA[5], eN[5]; float ZA = 0.f, ZN = 0.f;
            #pragma unroll
            for (int i = 0; i < 5; ++i) {
                eA[i] = __expf(lrelu(s1a[i] + s2a[j])); ZA += eA[i];
                eN[i] = __expf(lrelu(s1b[i] + s2b[j])); ZN += eN[i];
            }
            float rzA = __fdividef(1.f, ZA), rzN = __fdividef(1.f, ZN);
            #pragma unroll
            for (int i = 0; i < 5; ++i) {
                float wa = eA[i] * rzA, wn = eN[i] * rzN;
                fma2(oA2[i], pk2(wa, wa), hAj);
                fma2(oN2[i], pk2(wn, wn), hNj);
            }
        }
        u64 fa2[5], fb2[5];
        #pragma unroll
        for (int n = 0; n < 5; ++n) {
            float sc = g_CST[16 + n], bi = g_CST[24 + n];
            float2 a = upk2(oA2[n]), b = upk2(oN2[n]);
            fa2[n] = pk2(fmaxf(fmaf(a.x, sc, bi), 0.f), fmaxf(fmaf(a.y, sc, bi), 0.f));
            fb2[n] = pk2(fmaxf(fmaf(b.x, sc, bi), 0.f), fmaxf(fmaf(b.y, sc, bi), 0.f));
        }
        const ulonglong2* WLP = (const ulonglong2*)g_WLP4;
        float ov = 0.f;
        #pragma unroll
        for (int c = 0; c < 13; ++c) {
            u64 a2 = 0ull;
            #pragma unroll
            for (int n = 0; n < 5; ++n) {
                ulonglong2 wl = WLP[(c * 5 + n) * 16 + m];
                fma2(a2, fa2[n], wl.x);
                fma2(a2, fb2[n], wl.y);
            }
            float2 p = upk2(a2);
            float v = p.x + p.y;
            v += __shfl_xor_sync(0xffffffffu, v, 8);
            v += __shfl_xor_sync(0xffffffffu, v, 4);
            v += __shfl_xor_sync(0xffffffffu, v, 2);
            v += __shfl_xor_sync(0xffffffffu, v, 1);
            if (m == c) ov = v;
        }
        int bb = b0 + u;
        if (m < 13 && bb < B)
            out[(size_t)bb * 13 + m] = ov + g_CST[32 + m];
    }
}

extern "C" void kernel_launch(void* const* d_in, const int* in_sizes, int n_in,
                              void* d_out, int out_size)
{
    const float* x   = (const float*)d_in[0];
    const float* Wt1 = (const float*)d_in[1];
    const float* a11 = (const float*)d_in[2];
    const float* a21 = (const float*)d_in[3];
    const float* g1  = (const float*)d_in[4];
    const float* b1  = (const float*)d_in[5];
    const float* m1  = (const float*)d_in[6];
    const float* v1  = (const float*)d_in[7];
    const float* Wt2 = (const float*)d_in[8];
    const float* a12 = (const float*)d_in[9];
    const float* a22 = (const float*)d_in[10];
    const float* g2  = (const float*)d_in[11];
    const float* b2  = (const float*)d_in[12];
    const float* m2  = (const float*)d_in[13];
    const float* v2  = (const float*)d_in[14];
    const float* Wl  = (const float*)d_in[15];
    const float* bl  = (const float*)d_in[16];

    int B = in_sizes[0] / 1250;
    prep<<<1, 1024>>>(Wt1, a11, a21, Wt2, a12, a22, Wl, bl,
                      g1, b1, m1, v1, g2, b2, m2, v2);
    int grid = (B + GROUP - 1) / GROUP;
    cudaFuncSetAttribute(gat15_kernel, cudaFuncAttributeMaxDynamicSharedMemorySize, SMEM_BYTES);
    cudaFuncSetAttribute(gat15_kernel, cudaFuncAttributePreferredSharedMemoryCarveout, 100);
    gat15_kernel<<<grid, NTHR, SMEM_BYTES>>>(x, (float*)d_out, B);
}